// round 1
// baseline (speedup 1.0000x reference)
#include <cuda_runtime.h>
#include <math.h>

// ---------------- static scratch (no allocations allowed) ----------------
__device__ float g_xn  [4*4096*512];
__device__ float g_qkv [4*4096*1536];
__device__ float g_ql  [32*256*64];
__device__ float g_kl  [32*256*64];
__device__ float g_sim1[32*4096*256];   // -> a1 after softmax
__device__ float g_sim3[32*256*4096];   // -> a3 after softmax
__device__ float g_a2  [32*256*256];
__device__ float g_z   [32*256*256];
__device__ float g_z2  [32*256*256];
__device__ float g_W   [32*256*256];
__device__ float g_U   [32*256*256];
__device__ float g_V2  [32*256*256];
__device__ float g_P2  [32*256*256];
__device__ float g_a3v [32*256*64];
__device__ float g_t   [32*256*64];
__device__ float g_outh[32*4096*64];
__device__ float g_cat [4*4096*512];
__device__ float g_red [2];

// ---------------- LayerNorm ----------------
__global__ void ln_kernel(const float* __restrict__ x, const float* __restrict__ gamma,
                          const float* __restrict__ beta, float* __restrict__ xn) {
    long row = blockIdx.x;
    const float* xr = x + row * 512;
    int t = threadIdx.x;
    float v0 = xr[t], v1 = xr[t + 256];
    __shared__ float red[256];
    red[t] = v0 + v1; __syncthreads();
    for (int s = 128; s; s >>= 1) { if (t < s) red[t] += red[t + s]; __syncthreads(); }
    float mu = red[0] * (1.f / 512.f); __syncthreads();
    float d0 = v0 - mu, d1 = v1 - mu;
    red[t] = d0 * d0 + d1 * d1; __syncthreads();
    for (int s = 128; s; s >>= 1) { if (t < s) red[t] += red[t + s]; __syncthreads(); }
    float rstd = rsqrtf(red[0] * (1.f / 512.f) + 1e-5f);
    float* o = xn + row * 512;
    o[t]       = d0 * rstd * gamma[t]       + beta[t];
    o[t + 256] = d1 * rstd * gamma[t + 256] + beta[t + 256];
}

// ---------------- generic batched 64x64x16 fp32 GEMM ----------------
// C[M,N] = op(A[M,K] x B), B either NN (B[k*ldb+c]) or NT (B[c*ldb+k]).
// Batch z in [0, gridDim.z): ptr += (z/8)*s?b + (z%8)*s?h.
// MODE 0: C=acc
// MODE 1: qkv epilogue, cols<512 scaled by 0.125 (q * dh^-0.5)
// MODE 2: C = alpha*acc + dscale*I  (square, r==c in-matrix)
// MODE 3: C = acc + bias[c] + resid[r*ldc+c]
template<bool BT, int MODE>
__global__ void __launch_bounds__(256)
gemm64(const float* __restrict__ A, int lda, long sAb, long sAh,
       const float* __restrict__ B, int ldb, long sBb, long sBh,
       float* __restrict__ C, int ldc, long sCb, long sCh,
       int K, float alpha, float dscale,
       const float* __restrict__ bias, const float* __restrict__ resid) {
    int z = blockIdx.z;
    A += (long)(z >> 3) * sAb + (long)(z & 7) * sAh;
    B += (long)(z >> 3) * sBb + (long)(z & 7) * sBh;
    C += (long)(z >> 3) * sCb + (long)(z & 7) * sCh;
    const int row0 = blockIdx.y << 6, col0 = blockIdx.x << 6;
    __shared__ __align__(16) float As[16][64];
    __shared__ __align__(16) float Bs[16][64];
    int tid = threadIdx.x;
    int tx = tid & 15, ty = tid >> 4;
    int lm = tid >> 2, lk = (tid & 3) << 2;
    float acc[4][4] = {};
    for (int k0 = 0; k0 < K; k0 += 16) {
        float4 a4 = *(const float4*)(A + (long)(row0 + lm) * lda + k0 + lk);
        As[lk + 0][lm] = a4.x; As[lk + 1][lm] = a4.y;
        As[lk + 2][lm] = a4.z; As[lk + 3][lm] = a4.w;
        if (BT) {
            float4 b4 = *(const float4*)(B + (long)(col0 + lm) * ldb + k0 + lk);
            Bs[lk + 0][lm] = b4.x; Bs[lk + 1][lm] = b4.y;
            Bs[lk + 2][lm] = b4.z; Bs[lk + 3][lm] = b4.w;
        } else {
            int kr = tid >> 4, nc = (tid & 15) << 2;
            float4 b4 = *(const float4*)(B + (long)(k0 + kr) * ldb + col0 + nc);
            *(float4*)&Bs[kr][nc] = b4;
        }
        __syncthreads();
#pragma unroll
        for (int k = 0; k < 16; k++) {
            float4 av = *(const float4*)&As[k][ty << 2];
            float4 bv = *(const float4*)&Bs[k][tx << 2];
            float a_[4] = {av.x, av.y, av.z, av.w};
            float b_[4] = {bv.x, bv.y, bv.z, bv.w};
#pragma unroll
            for (int i = 0; i < 4; i++)
#pragma unroll
                for (int j = 0; j < 4; j++)
                    acc[i][j] += a_[i] * b_[j];
        }
        __syncthreads();
    }
#pragma unroll
    for (int i = 0; i < 4; i++) {
        int r = row0 + (ty << 2) + i;
#pragma unroll
        for (int j = 0; j < 4; j++) {
            int c = col0 + (tx << 2) + j;
            float v = acc[i][j];
            if (MODE == 1) { if (c < 512) v *= 0.125f; }
            if (MODE == 2) { v = alpha * v + ((r == c) ? dscale : 0.f); }
            if (MODE == 3) { v = v + bias[c] + resid[(long)r * ldc + c]; }
            C[(long)r * ldc + c] = v;
        }
    }
}

// ---------------- landmarks: mean over 16 contiguous tokens ----------------
__global__ void landmark_kernel(const float* __restrict__ qkv,
                                float* __restrict__ ql, float* __restrict__ kl) {
    int mi = blockIdx.x, z = blockIdx.y;
    int b = z >> 3, h = z & 7;
    int d = threadIdx.x;
    long base = ((long)(b * 4096 + mi * 16)) * 1536 + h * 64 + d;
    float sq = 0.f, sk = 0.f;
#pragma unroll
    for (int t = 0; t < 16; t++) {
        sq += qkv[base + (long)t * 1536];
        sk += qkv[base + (long)t * 1536 + 512];
    }
    long o = ((long)z * 256 + mi) * 64 + d;
    ql[o] = sq * 0.0625f;
    kl[o] = sk * 0.0625f;
}

// ---------------- row softmax (row length = CNT*256) ----------------
template<int CNT>
__global__ void softmax_kernel(float* __restrict__ p) {
    p += (long)blockIdx.x * (CNT * 256);
    int t = threadIdx.x;
    float v[CNT];
    float lm = -1e30f;
#pragma unroll
    for (int i = 0; i < CNT; i++) { v[i] = p[t + i * 256]; lm = fmaxf(lm, v[i]); }
    __shared__ float red[256];
    red[t] = lm; __syncthreads();
    for (int s = 128; s; s >>= 1) { if (t < s) red[t] = fmaxf(red[t], red[t + s]); __syncthreads(); }
    float m = red[0]; __syncthreads();
    float ls = 0.f;
#pragma unroll
    for (int i = 0; i < CNT; i++) { v[i] = expf(v[i] - m); ls += v[i]; }
    red[t] = ls; __syncthreads();
    for (int s = 128; s; s >>= 1) { if (t < s) red[t] += red[t + s]; __syncthreads(); }
    float inv = 1.f / red[0];
#pragma unroll
    for (int i = 0; i < CNT; i++) p[t + i * 256] = v[i] * inv;
}

// ---------------- pinv init ----------------
__global__ void zero2(float* r) { r[0] = 0.f; r[1] = 0.f; }

__global__ void pinv_norms(const float* __restrict__ a2, float* __restrict__ red) {
    int z = blockIdx.x, t = threadIdx.x;
    const float* a = a2 + (long)z * 65536;
    float cs = 0.f, rs = 0.f;
    for (int i = 0; i < 256; i++) cs += fabsf(a[i * 256 + t]);   // column sum t
    for (int j = 0; j < 256; j++) rs += fabsf(a[t * 256 + j]);   // row sum t
    __shared__ float s1[256], s2[256];
    s1[t] = cs; s2[t] = rs; __syncthreads();
    for (int s = 128; s; s >>= 1) {
        if (t < s) { s1[t] = fmaxf(s1[t], s1[t + s]); s2[t] = fmaxf(s2[t], s2[t + s]); }
        __syncthreads();
    }
    if (t == 0) {   // values are positive -> int-bit atomicMax is order-preserving
        atomicMax((int*)&red[0], __float_as_int(s2[0]));   // col = sum(-1).max()
        atomicMax((int*)&red[1], __float_as_int(s1[0]));   // row = sum(-2).max()
    }
}

__global__ void build_z0(const float* __restrict__ a2, float* __restrict__ z0,
                         const float* __restrict__ red) {
    float inv = 1.f / (red[0] * red[1]);
    long idx = (long)blockIdx.x * 256 + threadIdx.x;
    long z = idx >> 16;
    int r = (int)(idx & 65535);
    int i = r >> 8, j = r & 255;
    z0[(z << 16) + ((long)j << 8) + i] = a2[idx] * inv;   // transpose
}

__global__ void neg_diag7(const float* __restrict__ W, float* __restrict__ U) {
    long idx = (long)blockIdx.x * 256 + threadIdx.x;
    int r = (int)(idx & 65535);
    int i = r >> 8, j = r & 255;
    U[idx] = ((i == j) ? 7.f : 0.f) - W[idx];
}

// ---------------- depthwise conv residual + head re-layout ----------------
__global__ void conv_add_cat(const float* __restrict__ qkv, const float* __restrict__ cw,
                             const float* __restrict__ outh, float* __restrict__ cat) {
    __shared__ float vs[96][64];
    __shared__ float wv[33];
    int tile = blockIdx.x, h = blockIdx.y, b = blockIdx.z;
    int tid = threadIdx.x;
    if (tid < 33) wv[tid] = cw[h * 33 + tid];
    int i0 = tile * 64;
    for (int idx = tid; idx < 96 * 64; idx += 256) {
        int tt = idx >> 6, d = idx & 63;
        int tok = i0 - 16 + tt;
        float val = 0.f;
        if (tok >= 0 && tok < 4096)
            val = qkv[((long)(b * 4096 + tok)) * 1536 + 1024 + h * 64 + d];
        vs[tt][d] = val;
    }
    __syncthreads();
    int d = tid & 63, tr = tid >> 6;
    int z = b * 8 + h;
    for (int s = 0; s < 16; s++) {
        int tl = tr + s * 4;
        float acc = 0.f;
#pragma unroll
        for (int kk = 0; kk < 33; kk++) acc += wv[kk] * vs[tl + kk][d];
        int i = i0 + tl;
        float o = outh[((long)z * 4096 + i) * 64 + d] + acc;
        cat[((long)(b * 4096 + i)) * 512 + h * 64 + d] = o;
    }
}

// ---------------- launch ----------------
extern "C" void kernel_launch(void* const* d_in, const int* in_sizes, int n_in,
                              void* d_out, int out_size) {
    const float* x     = (const float*)d_in[0];
    const float* gamma = (const float*)d_in[1];
    const float* beta  = (const float*)d_in[2];
    const float* Wqkv  = (const float*)d_in[3];
    const float* Wout  = (const float*)d_in[4];
    const float* bout  = (const float*)d_in[5];
    const float* convw = (const float*)d_in[6];
    float* out = (float*)d_out;

    float *xn, *qkv, *ql, *kl, *s1, *s3, *a2, *z, *z2, *W, *U, *V2, *P2, *a3v, *tt, *oh, *cat, *red;
    cudaGetSymbolAddress((void**)&xn,  g_xn);
    cudaGetSymbolAddress((void**)&qkv, g_qkv);
    cudaGetSymbolAddress((void**)&ql,  g_ql);
    cudaGetSymbolAddress((void**)&kl,  g_kl);
    cudaGetSymbolAddress((void**)&s1,  g_sim1);
    cudaGetSymbolAddress((void**)&s3,  g_sim3);
    cudaGetSymbolAddress((void**)&a2,  g_a2);
    cudaGetSymbolAddress((void**)&z,   g_z);
    cudaGetSymbolAddress((void**)&z2,  g_z2);
    cudaGetSymbolAddress((void**)&W,   g_W);
    cudaGetSymbolAddress((void**)&U,   g_U);
    cudaGetSymbolAddress((void**)&V2,  g_V2);
    cudaGetSymbolAddress((void**)&P2,  g_P2);
    cudaGetSymbolAddress((void**)&a3v, g_a3v);
    cudaGetSymbolAddress((void**)&tt,  g_t);
    cudaGetSymbolAddress((void**)&oh,  g_outh);
    cudaGetSymbolAddress((void**)&cat, g_cat);
    cudaGetSymbolAddress((void**)&red, g_red);

    // 1) LayerNorm
    ln_kernel<<<16384, 256>>>(x, gamma, beta, xn);

    // 2) QKV projection: [16384,512] @ [512,1536], q-cols scaled by 0.125
    gemm64<false, 1><<<dim3(24, 256, 1), 256>>>(
        xn, 512, 0, 0, Wqkv, 1536, 0, 0, qkv, 1536, 0, 0, 512, 0.f, 0.f, nullptr, nullptr);

    // 3) landmarks q_l, k_l (means over 16-token groups)
    landmark_kernel<<<dim3(256, 32), 64>>>(qkv, ql, kl);

    // 4) sim1 = q @ k_l^T  (per bh: 4096x256, K=64)
    gemm64<true, 0><<<dim3(4, 64, 32), 256>>>(
        qkv, 1536, 6291456, 64, kl, 64, 131072, 16384,
        s1, 256, 8388608, 1048576, 64, 0.f, 0.f, nullptr, nullptr);
    // 5) sim2 = q_l @ k_l^T (256x256)
    gemm64<true, 0><<<dim3(4, 4, 32), 256>>>(
        ql, 64, 131072, 16384, kl, 64, 131072, 16384,
        a2, 256, 524288, 65536, 64, 0.f, 0.f, nullptr, nullptr);
    // 6) sim3 = q_l @ k^T (256x4096)
    gemm64<true, 0><<<dim3(64, 4, 32), 256>>>(
        ql, 64, 131072, 16384, qkv + 512, 1536, 6291456, 64,
        s3, 4096, 8388608, 1048576, 64, 0.f, 0.f, nullptr, nullptr);

    // 7) softmaxes
    softmax_kernel<1><<<131072, 256>>>(s1);
    softmax_kernel<1><<<8192, 256>>>(a2);
    softmax_kernel<16><<<8192, 256>>>(s3);

    // 8) pinv init: z0 = a2^T / (col*row)
    zero2<<<1, 1>>>(red);
    pinv_norms<<<32, 256>>>(a2, red);
    build_z0<<<8192, 256>>>(a2, z, red);

    // 9) 6 Newton-Schulz iterations
    float *zc = z, *zn = z2;
    for (int it = 0; it < 6; it++) {
        gemm64<false, 2><<<dim3(4, 4, 32), 256>>>(             // W = a2 @ z
            a2, 256, 524288, 65536, zc, 256, 524288, 65536,
            W, 256, 524288, 65536, 256, 1.f, 0.f, nullptr, nullptr);
        neg_diag7<<<8192, 256>>>(W, U);                        // U = 7I - W
        gemm64<false, 2><<<dim3(4, 4, 32), 256>>>(             // V2 = 15I - W@U
            W, 256, 524288, 65536, U, 256, 524288, 65536,
            V2, 256, 524288, 65536, 256, -1.f, 15.f, nullptr, nullptr);
        gemm64<false, 2><<<dim3(4, 4, 32), 256>>>(             // P2 = 13I - W@V2
            W, 256, 524288, 65536, V2, 256, 524288, 65536,
            P2, 256, 524288, 65536, 256, -1.f, 13.f, nullptr, nullptr);
        gemm64<false, 2><<<dim3(4, 4, 32), 256>>>(             // z' = 0.25 * z @ P2
            zc, 256, 524288, 65536, P2, 256, 524288, 65536,
            zn, 256, 524288, 65536, 256, 0.25f, 0.f, nullptr, nullptr);
        float* tmp = zc; zc = zn; zn = tmp;
    }

    // 10) a3v = a3 @ v  (256x64, K=4096)
    gemm64<false, 0><<<dim3(1, 4, 32), 256>>>(
        s3, 4096, 8388608, 1048576, qkv + 1024, 1536, 6291456, 64,
        a3v, 64, 131072, 16384, 4096, 0.f, 0.f, nullptr, nullptr);
    // 11) t = a2_inv @ a3v (256x64, K=256)
    gemm64<false, 0><<<dim3(1, 4, 32), 256>>>(
        zc, 256, 524288, 65536, a3v, 64, 131072, 16384,
        tt, 64, 131072, 16384, 256, 0.f, 0.f, nullptr, nullptr);
    // 12) out_h = a1 @ t (4096x64, K=256)
    gemm64<false, 0><<<dim3(1, 64, 32), 256>>>(
        s1, 256, 8388608, 1048576, tt, 64, 131072, 16384,
        oh, 64, 2097152, 262144, 256, 0.f, 0.f, nullptr, nullptr);

    // 13) depthwise conv residual + (b,h,n,d)->(b,n,h*d) re-layout
    conv_add_cat<<<dim3(64, 8, 4), 256>>>(qkv, convw, oh, cat);

    // 14) out = x + cat @ W_out + b_out
    gemm64<false, 3><<<dim3(8, 256, 1), 256>>>(
        cat, 512, 0, 0, Wout, 512, 0, 0, out, 512, 0, 0, 512, 0.f, 0.f, bout, x);
}

// round 2
// speedup vs baseline: 2.1449x; 2.1449x over previous
#include <cuda_runtime.h>
#include <math.h>
#include <stdint.h>

// ---------------- static scratch (no allocations allowed) ----------------
__device__ float g_xn  [4*4096*512];
__device__ float g_qkv [4*4096*1536];
__device__ float g_ql  [32*256*64];
__device__ float g_kl  [32*256*64];
__device__ float g_sim1[32*4096*256];   // -> a1 after softmax
__device__ float g_sim3[32*256*4096];   // -> a3 after softmax
__device__ float g_a2  [32*256*256];
__device__ float g_z   [32*256*256];
__device__ float g_z2  [32*256*256];
__device__ float g_W   [32*256*256];
__device__ float g_U   [32*256*256];
__device__ float g_V2  [32*256*256];
__device__ float g_P2  [32*256*256];
__device__ float g_a3v [32*256*64];
__device__ float g_t   [32*256*64];
__device__ float g_outh[32*4096*64];
__device__ float g_cat [4*4096*512];
__device__ float g_red [2];

// ---------------- helpers ----------------
__device__ __forceinline__ float tf32r(float x) {
    uint32_t u;
    asm("cvt.rna.tf32.f32 %0, %1;" : "=r"(u) : "f"(x));
    return __uint_as_float(u);
}

__device__ __forceinline__ void mma8(float* c, const uint32_t* a, const uint32_t* b) {
    asm volatile(
        "mma.sync.aligned.m16n8k8.row.col.f32.tf32.tf32.f32 "
        "{%0,%1,%2,%3}, {%4,%5,%6,%7}, {%8,%9}, {%0,%1,%2,%3};\n"
        : "+f"(c[0]), "+f"(c[1]), "+f"(c[2]), "+f"(c[3])
        : "r"(a[0]), "r"(a[1]), "r"(a[2]), "r"(a[3]), "r"(b[0]), "r"(b[1]));
}

// ---------------- LayerNorm ----------------
__global__ void ln_kernel(const float* __restrict__ x, const float* __restrict__ gamma,
                          const float* __restrict__ beta, float* __restrict__ xn) {
    long row = blockIdx.x;
    const float* xr = x + row * 512;
    int t = threadIdx.x;
    float v0 = xr[t], v1 = xr[t + 256];
    __shared__ float red[256];
    red[t] = v0 + v1; __syncthreads();
    for (int s = 128; s; s >>= 1) { if (t < s) red[t] += red[t + s]; __syncthreads(); }
    float mu = red[0] * (1.f / 512.f); __syncthreads();
    float d0 = v0 - mu, d1 = v1 - mu;
    red[t] = d0 * d0 + d1 * d1; __syncthreads();
    for (int s = 128; s; s >>= 1) { if (t < s) red[t] += red[t + s]; __syncthreads(); }
    float rstd = rsqrtf(red[0] * (1.f / 512.f) + 1e-5f);
    float* o = xn + row * 512;
    o[t]       = d0 * rstd * gamma[t]       + beta[t];
    o[t + 256] = d1 * rstd * gamma[t + 256] + beta[t + 256];
}

// ---------------- TF32 tensor-core batched GEMM ----------------
// C[M,N] = op(A[M,K] x B); B NN (B[k*ldb+c]) or BT (B[c*ldb+k]).
// Batch z: ptr += (z/8)*s?b + (z%8)*s?h.
// MODE 0: C=acc
// MODE 1: qkv epilogue (cols<512 scaled by 0.125)
// MODE 2: C = alpha*acc + dscale*I
// MODE 3: C = acc + bias[c] + resid[r*ldc+c]
template<int BM, int BN, int WR, int WC, bool BT, int MODE>
__global__ void __launch_bounds__(256)
gemmT(const float* __restrict__ A, int lda, long sAb, long sAh,
      const float* __restrict__ B, int ldb, long sBb, long sBh,
      float* __restrict__ C, int ldc, long sCb, long sCh,
      int K, float alpha, float dscale,
      const float* __restrict__ bias, const float* __restrict__ resid) {
    constexpr int WM = BM / WR, WN = BN / WC;
    constexpr int MT = WM / 16, NT = WN / 8;
    constexpr int AP = 20;        // A smem pitch: [BM][AP], k-inner
    constexpr int BP = BN + 4;    // B smem pitch: [16][BP], n-inner
    constexpr int AIT = BM * 16 / 1024;   // float4 loads per thread for A
    constexpr int BIT = BN * 16 / 1024;   // for B

    __shared__ float As[BM][AP];
    __shared__ float Bs[16][BP];

    int z = blockIdx.z;
    A += (long)(z >> 3) * sAb + (long)(z & 7) * sAh;
    B += (long)(z >> 3) * sBb + (long)(z & 7) * sBh;
    C += (long)(z >> 3) * sCb + (long)(z & 7) * sCh;

    const int row0 = blockIdx.y * BM, col0 = blockIdx.x * BN;
    const int tid = threadIdx.x, lane = tid & 31, wid = tid >> 5;
    const int wr = wid % WR, wc = wid / WR;
    const int g = lane >> 2, t4 = lane & 3;

    float acc[MT][NT][4];
#pragma unroll
    for (int i = 0; i < MT; i++)
#pragma unroll
        for (int j = 0; j < NT; j++)
#pragma unroll
            for (int e = 0; e < 4; e++) acc[i][j][e] = 0.f;

    float4 ra[AIT], rb[BIT];

    auto ldg = [&](int k0) {
#pragma unroll
        for (int i = 0; i < AIT; i++) {
            int idx = tid + i * 256;
            int r = idx >> 2, c4 = (idx & 3) << 2;
            ra[i] = *(const float4*)(A + (long)(row0 + r) * lda + k0 + c4);
        }
        if (BT) {
#pragma unroll
            for (int i = 0; i < BIT; i++) {
                int idx = tid + i * 256;
                int n = idx >> 2, c4 = (idx & 3) << 2;
                rb[i] = *(const float4*)(B + (long)(col0 + n) * ldb + k0 + c4);
            }
        } else {
#pragma unroll
            for (int i = 0; i < BIT; i++) {
                int idx = tid + i * 256;
                int r  = (BIT == 2) ? (idx >> 5) : (idx >> 4);
                int n4 = (BIT == 2) ? ((idx & 31) << 2) : ((idx & 15) << 2);
                rb[i] = *(const float4*)(B + (long)(k0 + r) * ldb + col0 + n4);
            }
        }
    };

    auto sts = [&]() {
#pragma unroll
        for (int i = 0; i < AIT; i++) {
            int idx = tid + i * 256;
            int r = idx >> 2, c4 = (idx & 3) << 2;
            float4 v = ra[i];
            v.x = tf32r(v.x); v.y = tf32r(v.y); v.z = tf32r(v.z); v.w = tf32r(v.w);
            *(float4*)&As[r][c4] = v;
        }
        if (BT) {
#pragma unroll
            for (int i = 0; i < BIT; i++) {
                int idx = tid + i * 256;
                int n = idx >> 2, c4 = (idx & 3) << 2;
                Bs[c4 + 0][n] = tf32r(rb[i].x);
                Bs[c4 + 1][n] = tf32r(rb[i].y);
                Bs[c4 + 2][n] = tf32r(rb[i].z);
                Bs[c4 + 3][n] = tf32r(rb[i].w);
            }
        } else {
#pragma unroll
            for (int i = 0; i < BIT; i++) {
                int idx = tid + i * 256;
                int r  = (BIT == 2) ? (idx >> 5) : (idx >> 4);
                int n4 = (BIT == 2) ? ((idx & 31) << 2) : ((idx & 15) << 2);
                float4 v = rb[i];
                v.x = tf32r(v.x); v.y = tf32r(v.y); v.z = tf32r(v.z); v.w = tf32r(v.w);
                *(float4*)&Bs[r][n4] = v;
            }
        }
    };

    ldg(0);
    for (int k0 = 0; k0 < K; k0 += 16) {
        sts();
        __syncthreads();
        if (k0 + 16 < K) ldg(k0 + 16);
#pragma unroll
        for (int k8 = 0; k8 < 16; k8 += 8) {
            uint32_t af[MT][4], bf[NT][2];
#pragma unroll
            for (int mt = 0; mt < MT; mt++) {
                int m0 = wr * WM + mt * 16 + g;
                af[mt][0] = __float_as_uint(As[m0    ][k8 + t4]);
                af[mt][1] = __float_as_uint(As[m0 + 8][k8 + t4]);
                af[mt][2] = __float_as_uint(As[m0    ][k8 + t4 + 4]);
                af[mt][3] = __float_as_uint(As[m0 + 8][k8 + t4 + 4]);
            }
#pragma unroll
            for (int nt = 0; nt < NT; nt++) {
                int n0 = wc * WN + nt * 8 + g;
                bf[nt][0] = __float_as_uint(Bs[k8 + t4    ][n0]);
                bf[nt][1] = __float_as_uint(Bs[k8 + t4 + 4][n0]);
            }
#pragma unroll
            for (int mt = 0; mt < MT; mt++)
#pragma unroll
                for (int nt = 0; nt < NT; nt++)
                    mma8(acc[mt][nt], af[mt], bf[nt]);
        }
        __syncthreads();
    }

    // epilogue
#pragma unroll
    for (int mt = 0; mt < MT; mt++) {
#pragma unroll
        for (int nt = 0; nt < NT; nt++) {
            int r = row0 + wr * WM + mt * 16 + g;
            int c = col0 + wc * WN + nt * 8 + 2 * t4;
#pragma unroll
            for (int half = 0; half < 2; half++) {
                int rr = r + half * 8;
                float v0 = acc[mt][nt][half * 2];
                float v1 = acc[mt][nt][half * 2 + 1];
                if (MODE == 1) { if (c < 512) { v0 *= 0.125f; v1 *= 0.125f; } }
                if (MODE == 2) {
                    v0 = alpha * v0 + ((rr == c)     ? dscale : 0.f);
                    v1 = alpha * v1 + ((rr == c + 1) ? dscale : 0.f);
                }
                if (MODE == 3) {
                    const float2 rx = *(const float2*)(resid + (long)rr * ldc + c);
                    v0 = v0 + bias[c]     + rx.x;
                    v1 = v1 + bias[c + 1] + rx.y;
                }
                float2 o; o.x = v0; o.y = v1;
                *(float2*)(C + (long)rr * ldc + c) = o;
            }
        }
    }
}

// ---------------- landmarks: mean over 16 contiguous tokens ----------------
__global__ void landmark_kernel(const float* __restrict__ qkv,
                                float* __restrict__ ql, float* __restrict__ kl) {
    int mi = blockIdx.x, z = blockIdx.y;
    int b = z >> 3, h = z & 7;
    int d = threadIdx.x;
    long base = ((long)(b * 4096 + mi * 16)) * 1536 + h * 64 + d;
    float sq = 0.f, sk = 0.f;
#pragma unroll
    for (int t = 0; t < 16; t++) {
        sq += qkv[base + (long)t * 1536];
        sk += qkv[base + (long)t * 1536 + 512];
    }
    long o = ((long)z * 256 + mi) * 64 + d;
    ql[o] = sq * 0.0625f;
    kl[o] = sk * 0.0625f;
}

// ---------------- row softmax (row length = CNT*256) ----------------
template<int CNT>
__global__ void softmax_kernel(float* __restrict__ p) {
    p += (long)blockIdx.x * (CNT * 256);
    int t = threadIdx.x;
    float v[CNT];
    float lm = -1e30f;
#pragma unroll
    for (int i = 0; i < CNT; i++) { v[i] = p[t + i * 256]; lm = fmaxf(lm, v[i]); }
    __shared__ float red[256];
    red[t] = lm; __syncthreads();
    for (int s = 128; s; s >>= 1) { if (t < s) red[t] = fmaxf(red[t], red[t + s]); __syncthreads(); }
    float m = red[0]; __syncthreads();
    float ls = 0.f;
#pragma unroll
    for (int i = 0; i < CNT; i++) { v[i] = expf(v[i] - m); ls += v[i]; }
    red[t] = ls; __syncthreads();
    for (int s = 128; s; s >>= 1) { if (t < s) red[t] += red[t + s]; __syncthreads(); }
    float inv = 1.f / red[0];
#pragma unroll
    for (int i = 0; i < CNT; i++) p[t + i * 256] = v[i] * inv;
}

// ---------------- pinv init ----------------
__global__ void zero2(float* r) { r[0] = 0.f; r[1] = 0.f; }

__global__ void pinv_norms(const float* __restrict__ a2, float* __restrict__ red) {
    int z = blockIdx.x, t = threadIdx.x;
    const float* a = a2 + (long)z * 65536;
    float cs = 0.f, rs = 0.f;
    for (int i = 0; i < 256; i++) cs += fabsf(a[i * 256 + t]);
    for (int j = 0; j < 256; j++) rs += fabsf(a[t * 256 + j]);
    __shared__ float s1[256], s2[256];
    s1[t] = cs; s2[t] = rs; __syncthreads();
    for (int s = 128; s; s >>= 1) {
        if (t < s) { s1[t] = fmaxf(s1[t], s1[t + s]); s2[t] = fmaxf(s2[t], s2[t + s]); }
        __syncthreads();
    }
    if (t == 0) {
        atomicMax((int*)&red[0], __float_as_int(s2[0]));   // col = sum(-1).max()
        atomicMax((int*)&red[1], __float_as_int(s1[0]));   // row = sum(-2).max()
    }
}

__global__ void build_z0(const float* __restrict__ a2, float* __restrict__ z0,
                         const float* __restrict__ red) {
    float inv = 1.f / (red[0] * red[1]);
    long idx = (long)blockIdx.x * 256 + threadIdx.x;
    long z = idx >> 16;
    int r = (int)(idx & 65535);
    int i = r >> 8, j = r & 255;
    z0[(z << 16) + ((long)j << 8) + i] = a2[idx] * inv;   // transpose
}

__global__ void neg_diag7(const float* __restrict__ W, float* __restrict__ U) {
    long idx = (long)blockIdx.x * 256 + threadIdx.x;
    int r = (int)(idx & 65535);
    int i = r >> 8, j = r & 255;
    U[idx] = ((i == j) ? 7.f : 0.f) - W[idx];
}

// ---------------- depthwise conv residual + head re-layout ----------------
__global__ void conv_add_cat(const float* __restrict__ qkv, const float* __restrict__ cw,
                             const float* __restrict__ outh, float* __restrict__ cat) {
    __shared__ float vs[96][64];
    __shared__ float wv[33];
    int tile = blockIdx.x, h = blockIdx.y, b = blockIdx.z;
    int tid = threadIdx.x;
    if (tid < 33) wv[tid] = cw[h * 33 + tid];
    int i0 = tile * 64;
    for (int idx = tid; idx < 96 * 64; idx += 256) {
        int tt = idx >> 6, d = idx & 63;
        int tok = i0 - 16 + tt;
        float val = 0.f;
        if (tok >= 0 && tok < 4096)
            val = qkv[((long)(b * 4096 + tok)) * 1536 + 1024 + h * 64 + d];
        vs[tt][d] = val;
    }
    __syncthreads();
    int d = tid & 63, tr = tid >> 6;
    int z = b * 8 + h;
    for (int s = 0; s < 16; s++) {
        int tl = tr + s * 4;
        float acc = 0.f;
#pragma unroll
        for (int kk = 0; kk < 33; kk++) acc += wv[kk] * vs[tl + kk][d];
        int i = i0 + tl;
        float o = outh[((long)z * 4096 + i) * 64 + d] + acc;
        cat[((long)(b * 4096 + i)) * 512 + h * 64 + d] = o;
    }
}

// ---------------- launch ----------------
extern "C" void kernel_launch(void* const* d_in, const int* in_sizes, int n_in,
                              void* d_out, int out_size) {
    const float* x     = (const float*)d_in[0];
    const float* gamma = (const float*)d_in[1];
    const float* beta  = (const float*)d_in[2];
    const float* Wqkv  = (const float*)d_in[3];
    const float* Wout  = (const float*)d_in[4];
    const float* bout  = (const float*)d_in[5];
    const float* convw = (const float*)d_in[6];
    float* out = (float*)d_out;

    float *xn, *qkv, *ql, *kl, *s1, *s3, *a2, *z, *z2, *W, *U, *V2, *P2, *a3v, *tt, *oh, *cat, *red;
    cudaGetSymbolAddress((void**)&xn,  g_xn);
    cudaGetSymbolAddress((void**)&qkv, g_qkv);
    cudaGetSymbolAddress((void**)&ql,  g_ql);
    cudaGetSymbolAddress((void**)&kl,  g_kl);
    cudaGetSymbolAddress((void**)&s1,  g_sim1);
    cudaGetSymbolAddress((void**)&s3,  g_sim3);
    cudaGetSymbolAddress((void**)&a2,  g_a2);
    cudaGetSymbolAddress((void**)&z,   g_z);
    cudaGetSymbolAddress((void**)&z2,  g_z2);
    cudaGetSymbolAddress((void**)&W,   g_W);
    cudaGetSymbolAddress((void**)&U,   g_U);
    cudaGetSymbolAddress((void**)&V2,  g_V2);
    cudaGetSymbolAddress((void**)&P2,  g_P2);
    cudaGetSymbolAddress((void**)&a3v, g_a3v);
    cudaGetSymbolAddress((void**)&tt,  g_t);
    cudaGetSymbolAddress((void**)&oh,  g_outh);
    cudaGetSymbolAddress((void**)&cat, g_cat);
    cudaGetSymbolAddress((void**)&red, g_red);

    // 1) LayerNorm
    ln_kernel<<<16384, 256>>>(x, gamma, beta, xn);

    // 2) QKV projection: [16384,512] @ [512,1536], q-cols scaled by 0.125
    gemmT<128,128,2,4,false,1><<<dim3(12, 128, 1), 256>>>(
        xn, 512, 0, 0, Wqkv, 1536, 0, 0, qkv, 1536, 0, 0, 512, 0.f, 0.f, nullptr, nullptr);

    // 3) landmarks
    landmark_kernel<<<dim3(256, 32), 64>>>(qkv, ql, kl);

    // 4) sim1 = q @ k_l^T  (per bh: 4096x256, K=64)
    gemmT<128,128,2,4,true,0><<<dim3(2, 32, 32), 256>>>(
        qkv, 1536, 6291456, 64, kl, 64, 131072, 16384,
        s1, 256, 8388608, 1048576, 64, 0.f, 0.f, nullptr, nullptr);
    // 5) sim2 = q_l @ k_l^T (256x256)
    gemmT<128,128,2,4,true,0><<<dim3(2, 2, 32), 256>>>(
        ql, 64, 131072, 16384, kl, 64, 131072, 16384,
        a2, 256, 524288, 65536, 64, 0.f, 0.f, nullptr, nullptr);
    // 6) sim3 = q_l @ k^T (256x4096)
    gemmT<128,128,2,4,true,0><<<dim3(32, 2, 32), 256>>>(
        ql, 64, 131072, 16384, qkv + 512, 1536, 6291456, 64,
        s3, 4096, 8388608, 1048576, 64, 0.f, 0.f, nullptr, nullptr);

    // 7) softmaxes
    softmax_kernel<1><<<131072, 256>>>(s1);
    softmax_kernel<1><<<8192, 256>>>(a2);
    softmax_kernel<16><<<8192, 256>>>(s3);

    // 8) pinv init: z0 = a2^T / (col*row)
    zero2<<<1, 1>>>(red);
    pinv_norms<<<32, 256>>>(a2, red);
    build_z0<<<8192, 256>>>(a2, z, red);

    // 9) 6 Newton-Schulz iterations
    float *zc = z, *zn = z2;
    for (int it = 0; it < 6; it++) {
        gemmT<128,128,2,4,false,2><<<dim3(2, 2, 32), 256>>>(             // W = a2 @ z
            a2, 256, 524288, 65536, zc, 256, 524288, 65536,
            W, 256, 524288, 65536, 256, 1.f, 0.f, nullptr, nullptr);
        neg_diag7<<<8192, 256>>>(W, U);                                   // U = 7I - W
        gemmT<128,128,2,4,false,2><<<dim3(2, 2, 32), 256>>>(             // V2 = 15I - W@U
            W, 256, 524288, 65536, U, 256, 524288, 65536,
            V2, 256, 524288, 65536, 256, -1.f, 15.f, nullptr, nullptr);
        gemmT<128,128,2,4,false,2><<<dim3(2, 2, 32), 256>>>(             // P2 = 13I - W@V2
            W, 256, 524288, 65536, V2, 256, 524288, 65536,
            P2, 256, 524288, 65536, 256, -1.f, 13.f, nullptr, nullptr);
        gemmT<128,128,2,4,false,2><<<dim3(2, 2, 32), 256>>>(             // z' = 0.25 * z @ P2
            zc, 256, 524288, 65536, P2, 256, 524288, 65536,
            zn, 256, 524288, 65536, 256, 0.25f, 0.f, nullptr, nullptr);
        float* tmp = zc; zc = zn; zn = tmp;
    }

    // 10) a3v = a3 @ v  (256x64, K=4096)
    gemmT<128,64,4,2,false,0><<<dim3(1, 2, 32), 256>>>(
        s3, 4096, 8388608, 1048576, qkv + 1024, 1536, 6291456, 64,
        a3v, 64, 131072, 16384, 4096, 0.f, 0.f, nullptr, nullptr);
    // 11) t = a2_inv @ a3v (256x64, K=256)
    gemmT<128,64,4,2,false,0><<<dim3(1, 2, 32), 256>>>(
        zc, 256, 524288, 65536, a3v, 64, 131072, 16384,
        tt, 64, 131072, 16384, 256, 0.f, 0.f, nullptr, nullptr);
    // 12) out_h = a1 @ t (4096x64, K=256)
    gemmT<128,64,4,2,false,0><<<dim3(1, 32, 32), 256>>>(
        s1, 256, 8388608, 1048576, tt, 64, 131072, 16384,
        oh, 64, 2097152, 262144, 256, 0.f, 0.f, nullptr, nullptr);

    // 13) depthwise conv residual + head re-layout
    conv_add_cat<<<dim3(64, 8, 4), 256>>>(qkv, convw, oh, cat);

    // 14) out = x + cat @ W_out + b_out
    gemmT<128,128,2,4,false,3><<<dim3(4, 128, 1), 256>>>(
        cat, 512, 0, 0, Wout, 512, 0, 0, out, 512, 0, 0, 512, 0.f, 0.f, bout, x);
}

// round 3
// speedup vs baseline: 2.5318x; 1.1804x over previous
#include <cuda_runtime.h>
#include <math.h>
#include <stdint.h>

// ---------------- static scratch (no allocations allowed) ----------------
__device__ float g_xn  [4*4096*512];
__device__ float g_qkv [4*4096*1536];
__device__ float g_ql  [32*256*64];
__device__ float g_kl  [32*256*64];
__device__ float g_sim1[32*4096*256];   // raw scores (softmax fused into consumer)
__device__ float g_sim3[32*256*4096];   // raw scores
__device__ float g_a2  [32*256*256];
__device__ float g_z   [32*256*256];
__device__ float g_z2  [32*256*256];
__device__ float g_W   [32*256*256];
__device__ float g_U   [32*256*256];
__device__ float g_V2  [32*256*256];
__device__ float g_P2  [32*256*256];
__device__ float g_a3v [32*256*64];
__device__ float g_t   [32*256*64];
__device__ float g_outh[32*4096*64];
__device__ float g_cat [4*4096*512];
__device__ float g_red [2];
__device__ float2 g_rs1[32*4096];       // row stats (max, 1/sum) for sim1
__device__ float2 g_rs3[32*256];        // row stats for sim3

// ---------------- helpers ----------------
__device__ __forceinline__ float tf32r(float x) {
    uint32_t u;
    asm("cvt.rna.tf32.f32 %0, %1;" : "=r"(u) : "f"(x));
    return __uint_as_float(u);
}

__device__ __forceinline__ void mma8(float* c, const uint32_t* a, const uint32_t* b) {
    asm volatile(
        "mma.sync.aligned.m16n8k8.row.col.f32.tf32.tf32.f32 "
        "{%0,%1,%2,%3}, {%4,%5,%6,%7}, {%8,%9}, {%0,%1,%2,%3};\n"
        : "+f"(c[0]), "+f"(c[1]), "+f"(c[2]), "+f"(c[3])
        : "r"(a[0]), "r"(a[1]), "r"(a[2]), "r"(a[3]), "r"(b[0]), "r"(b[1]));
}

__device__ __forceinline__ void ldsm4(uint32_t* r, uint32_t addr) {
    asm volatile("ldmatrix.sync.aligned.m8n8.x4.shared.b16 {%0,%1,%2,%3}, [%4];\n"
        : "=r"(r[0]), "=r"(r[1]), "=r"(r[2]), "=r"(r[3]) : "r"(addr));
}

// ---------------- LayerNorm ----------------
__global__ void ln_kernel(const float* __restrict__ x, const float* __restrict__ gamma,
                          const float* __restrict__ beta, float* __restrict__ xn) {
    long row = blockIdx.x;
    const float* xr = x + row * 512;
    int t = threadIdx.x;
    float v0 = xr[t], v1 = xr[t + 256];
    __shared__ float red[256];
    red[t] = v0 + v1; __syncthreads();
    for (int s = 128; s; s >>= 1) { if (t < s) red[t] += red[t + s]; __syncthreads(); }
    float mu = red[0] * (1.f / 512.f); __syncthreads();
    float d0 = v0 - mu, d1 = v1 - mu;
    red[t] = d0 * d0 + d1 * d1; __syncthreads();
    for (int s = 128; s; s >>= 1) { if (t < s) red[t] += red[t + s]; __syncthreads(); }
    float rstd = rsqrtf(red[0] * (1.f / 512.f) + 1e-5f);
    float* o = xn + row * 512;
    o[t]       = d0 * rstd * gamma[t]       + beta[t];
    o[t + 256] = d1 * rstd * gamma[t + 256] + beta[t + 256];
}

// ---------------- TF32 tensor-core batched GEMM ----------------
// MODE 0: C=acc
// MODE 1: qkv epilogue (cols<512 scaled by 0.125)
// MODE 2: C = alpha*acc + dscale*I
// MODE 3: C = acc + bias[c] + resid[r*ldc+c]
// MODE 4: C = acc ; Caux = dscale*I - acc
// SMX:    A element transform a -> exp(a - stat.x)*stat.y (row softmax fused on load)
// ATOM:   blockIdx.x = K-split segment; epilogue atomicAdd into C (C pre-zeroed)
template<int BM, int BN, int WR, int WC, bool BT, int MODE, bool SMX, bool ATOM>
__global__ void __launch_bounds__(256)
gemmT(const float* __restrict__ A, int lda, long sAb, long sAh,
      const float* __restrict__ B, int ldb, long sBb, long sBh,
      float* __restrict__ C, int ldc, long sCb, long sCh,
      int K, float alpha, float dscale,
      const float* __restrict__ bias, const float* __restrict__ resid,
      float* __restrict__ Caux, const float2* __restrict__ stats, long statStride) {
    constexpr int WM = BM / WR, WN = BN / WC;
    constexpr int MT = WM / 16, NT = WN / 8;
    constexpr int AP = 20;        // A smem pitch: [BM][AP], k-inner
    constexpr int BP = BN + 8;    // B smem pitch: [16][BP], n-inner (conflict-free frag LDS)
    constexpr int AIT = BM * 16 / 1024;
    constexpr int BIT = BN * 16 / 1024;

    __shared__ __align__(16) float As[BM][AP];
    __shared__ __align__(16) float Bs[16][BP];

    int z = blockIdx.z;
    A += (long)(z >> 3) * sAb + (long)(z & 7) * sAh;
    B += (long)(z >> 3) * sBb + (long)(z & 7) * sBh;
    C += (long)(z >> 3) * sCb + (long)(z & 7) * sCh;
    if (MODE == 4) Caux += (long)(z >> 3) * sCb + (long)(z & 7) * sCh;
    if (SMX) stats += (long)z * statStride;

    int col0;
    if (ATOM) {       // K-split: blockIdx.x selects k-segment, single N block
        col0 = 0;
        A += (long)blockIdx.x * K;
        if (BT) B += (long)blockIdx.x * K;
        else    B += (long)blockIdx.x * K * ldb;
    } else {
        col0 = blockIdx.x * BN;
    }
    const int row0 = blockIdx.y * BM;
    const int tid = threadIdx.x, lane = tid & 31, wid = tid >> 5;
    const int wr = wid % WR, wc = wid / WR;
    const int g = lane >> 2, t4 = lane & 3;
    const int lrow = (lane & 7) + ((lane >> 3) & 1) * 8;   // ldmatrix row offset
    const int lcol = ((lane >> 4) & 1) * 4;                 // ldmatrix col offset
    const uint32_t asBase = (uint32_t)__cvta_generic_to_shared(&As[0][0]);

    float acc[MT][NT][4];
#pragma unroll
    for (int i = 0; i < MT; i++)
#pragma unroll
        for (int j = 0; j < NT; j++)
#pragma unroll
            for (int e = 0; e < 4; e++) acc[i][j][e] = 0.f;

    float4 ra[AIT], rb[BIT];
    float2 rst[AIT];
    if (SMX) {
#pragma unroll
        for (int i = 0; i < AIT; i++) {
            int idx = tid + i * 256;
            rst[i] = stats[row0 + (idx >> 2)];
        }
    }

    auto ldg = [&](int k0) {
#pragma unroll
        for (int i = 0; i < AIT; i++) {
            int idx = tid + i * 256;
            int r = idx >> 2, c4 = (idx & 3) << 2;
            ra[i] = *(const float4*)(A + (long)(row0 + r) * lda + k0 + c4);
        }
        if (BT) {
#pragma unroll
            for (int i = 0; i < BIT; i++) {
                int idx = tid + i * 256;
                int n = idx >> 2, c4 = (idx & 3) << 2;
                rb[i] = *(const float4*)(B + (long)(col0 + n) * ldb + k0 + c4);
            }
        } else {
#pragma unroll
            for (int i = 0; i < BIT; i++) {
                int idx = tid + i * 256;
                int r  = (BIT == 2) ? (idx >> 5) : (idx >> 4);
                int n4 = (BIT == 2) ? ((idx & 31) << 2) : ((idx & 15) << 2);
                rb[i] = *(const float4*)(B + (long)(k0 + r) * ldb + col0 + n4);
            }
        }
    };

    auto sts = [&]() {
#pragma unroll
        for (int i = 0; i < AIT; i++) {
            int idx = tid + i * 256;
            int r = idx >> 2, c4 = (idx & 3) << 2;
            float4 v = ra[i];
            if (SMX) {
                v.x = __expf(v.x - rst[i].x) * rst[i].y;
                v.y = __expf(v.y - rst[i].x) * rst[i].y;
                v.z = __expf(v.z - rst[i].x) * rst[i].y;
                v.w = __expf(v.w - rst[i].x) * rst[i].y;
            }
            v.x = tf32r(v.x); v.y = tf32r(v.y); v.z = tf32r(v.z); v.w = tf32r(v.w);
            *(float4*)&As[r][c4] = v;
        }
        if (BT) {
#pragma unroll
            for (int i = 0; i < BIT; i++) {
                int idx = tid + i * 256;
                int n = idx >> 2, c4 = (idx & 3) << 2;
                Bs[c4 + 0][n] = tf32r(rb[i].x);
                Bs[c4 + 1][n] = tf32r(rb[i].y);
                Bs[c4 + 2][n] = tf32r(rb[i].z);
                Bs[c4 + 3][n] = tf32r(rb[i].w);
            }
        } else {
#pragma unroll
            for (int i = 0; i < BIT; i++) {
                int idx = tid + i * 256;
                int r  = (BIT == 2) ? (idx >> 5) : (idx >> 4);
                int n4 = (BIT == 2) ? ((idx & 31) << 2) : ((idx & 15) << 2);
                float4 v = rb[i];
                v.x = tf32r(v.x); v.y = tf32r(v.y); v.z = tf32r(v.z); v.w = tf32r(v.w);
                *(float4*)&Bs[r][n4] = v;
            }
        }
    };

    ldg(0);
    for (int k0 = 0; k0 < K; k0 += 16) {
        sts();
        __syncthreads();
        if (k0 + 16 < K) ldg(k0 + 16);
#pragma unroll
        for (int k8 = 0; k8 < 16; k8 += 8) {
            uint32_t af[MT][4], bf[NT][2];
#pragma unroll
            for (int mt = 0; mt < MT; mt++) {
                int row = wr * WM + mt * 16 + lrow;
                ldsm4(af[mt], asBase + (uint32_t)((row * AP + lcol + k8) << 2));
            }
#pragma unroll
            for (int nt = 0; nt < NT; nt++) {
                int n0 = wc * WN + nt * 8 + g;
                bf[nt][0] = __float_as_uint(Bs[k8 + t4    ][n0]);
                bf[nt][1] = __float_as_uint(Bs[k8 + t4 + 4][n0]);
            }
#pragma unroll
            for (int mt = 0; mt < MT; mt++)
#pragma unroll
                for (int nt = 0; nt < NT; nt++)
                    mma8(acc[mt][nt], af[mt], bf[nt]);
        }
        __syncthreads();
    }

    // epilogue
#pragma unroll
    for (int mt = 0; mt < MT; mt++) {
#pragma unroll
        for (int nt = 0; nt < NT; nt++) {
            int r = row0 + wr * WM + mt * 16 + g;
            int c = col0 + wc * WN + nt * 8 + 2 * t4;
#pragma unroll
            for (int half = 0; half < 2; half++) {
                int rr = r + half * 8;
                float v0 = acc[mt][nt][half * 2];
                float v1 = acc[mt][nt][half * 2 + 1];
                if (MODE == 1) { if (c < 512) { v0 *= 0.125f; v1 *= 0.125f; } }
                if (MODE == 2) {
                    v0 = alpha * v0 + ((rr == c)     ? dscale : 0.f);
                    v1 = alpha * v1 + ((rr == c + 1) ? dscale : 0.f);
                }
                if (MODE == 3) {
                    const float2 rx = *(const float2*)(resid + (long)rr * ldc + c);
                    v0 = v0 + bias[c]     + rx.x;
                    v1 = v1 + bias[c + 1] + rx.y;
                }
                if (ATOM) {
                    atomicAdd(&C[(long)rr * ldc + c],     v0);
                    atomicAdd(&C[(long)rr * ldc + c + 1], v1);
                } else {
                    float2 o; o.x = v0; o.y = v1;
                    *(float2*)(C + (long)rr * ldc + c) = o;
                    if (MODE == 4) {
                        float2 u;
                        u.x = ((rr == c)     ? dscale : 0.f) - v0;
                        u.y = ((rr == c + 1) ? dscale : 0.f) - v1;
                        *(float2*)(Caux + (long)rr * ldc + c) = u;
                    }
                }
            }
        }
    }
}

// ---------------- landmarks: mean over 16 contiguous tokens ----------------
__global__ void landmark_kernel(const float* __restrict__ qkv,
                                float* __restrict__ ql, float* __restrict__ kl) {
    int mi = blockIdx.x, z = blockIdx.y;
    int b = z >> 3, h = z & 7;
    int d = threadIdx.x;
    long base = ((long)(b * 4096 + mi * 16)) * 1536 + h * 64 + d;
    float sq = 0.f, sk = 0.f;
#pragma unroll
    for (int t = 0; t < 16; t++) {
        sq += qkv[base + (long)t * 1536];
        sk += qkv[base + (long)t * 1536 + 512];
    }
    long o = ((long)z * 256 + mi) * 64 + d;
    ql[o] = sq * 0.0625f;
    kl[o] = sk * 0.0625f;
}

// ---------------- row softmax (in-place, materialized) ----------------
template<int CNT>
__global__ void softmax_kernel(float* __restrict__ p) {
    p += (long)blockIdx.x * (CNT * 256);
    int t = threadIdx.x;
    float v[CNT];
    float lm = -1e30f;
#pragma unroll
    for (int i = 0; i < CNT; i++) { v[i] = p[t + i * 256]; lm = fmaxf(lm, v[i]); }
    __shared__ float red[256];
    red[t] = lm; __syncthreads();
    for (int s = 128; s; s >>= 1) { if (t < s) red[t] = fmaxf(red[t], red[t + s]); __syncthreads(); }
    float m = red[0]; __syncthreads();
    float ls = 0.f;
#pragma unroll
    for (int i = 0; i < CNT; i++) { v[i] = expf(v[i] - m); ls += v[i]; }
    red[t] = ls; __syncthreads();
    for (int s = 128; s; s >>= 1) { if (t < s) red[t] += red[t + s]; __syncthreads(); }
    float inv = 1.f / red[0];
#pragma unroll
    for (int i = 0; i < CNT; i++) p[t + i * 256] = v[i] * inv;
}

// ---------------- row stats (max, 1/sum exp) without materializing softmax ----
template<int CNT>
__global__ void rowstat_kernel(const float* __restrict__ p, float2* __restrict__ st) {
    p += (long)blockIdx.x * (CNT * 256);
    int t = threadIdx.x;
    float v[CNT];
    float lm = -1e30f;
#pragma unroll
    for (int i = 0; i < CNT; i++) { v[i] = p[t + i * 256]; lm = fmaxf(lm, v[i]); }
    __shared__ float red[256];
    red[t] = lm; __syncthreads();
    for (int s = 128; s; s >>= 1) { if (t < s) red[t] = fmaxf(red[t], red[t + s]); __syncthreads(); }
    float m = red[0]; __syncthreads();
    float ls = 0.f;
#pragma unroll
    for (int i = 0; i < CNT; i++) ls += __expf(v[i] - m);
    red[t] = ls; __syncthreads();
    for (int s = 128; s; s >>= 1) { if (t < s) red[t] += red[t + s]; __syncthreads(); }
    if (t == 0) { float2 o; o.x = m; o.y = 1.f / red[0]; st[blockIdx.x] = o; }
}

// ---------------- pinv init ----------------
__global__ void zero2(float* r) { r[0] = 0.f; r[1] = 0.f; }

__global__ void pinv_norms(const float* __restrict__ a2, float* __restrict__ red) {
    int z = blockIdx.x, t = threadIdx.x;
    const float* a = a2 + (long)z * 65536;
    float cs = 0.f, rs = 0.f;
    for (int i = 0; i < 256; i++) cs += fabsf(a[i * 256 + t]);
    for (int j = 0; j < 256; j++) rs += fabsf(a[t * 256 + j]);
    __shared__ float s1[256], s2[256];
    s1[t] = cs; s2[t] = rs; __syncthreads();
    for (int s = 128; s; s >>= 1) {
        if (t < s) { s1[t] = fmaxf(s1[t], s1[t + s]); s2[t] = fmaxf(s2[t], s2[t + s]); }
        __syncthreads();
    }
    if (t == 0) {
        atomicMax((int*)&red[0], __float_as_int(s2[0]));   // col = sum(-1).max()
        atomicMax((int*)&red[1], __float_as_int(s1[0]));   // row = sum(-2).max()
    }
}

__global__ void build_z0(const float* __restrict__ a2, float* __restrict__ z0,
                         const float* __restrict__ red) {
    float inv = 1.f / (red[0] * red[1]);
    long idx = (long)blockIdx.x * 256 + threadIdx.x;
    long z = idx >> 16;
    int r = (int)(idx & 65535);
    int i = r >> 8, j = r & 255;
    z0[(z << 16) + ((long)j << 8) + i] = a2[idx] * inv;   // transpose
}

// ---------------- depthwise conv residual + head re-layout ----------------
__global__ void conv_add_cat(const float* __restrict__ qkv, const float* __restrict__ cw,
                             const float* __restrict__ outh, float* __restrict__ cat) {
    __shared__ float vs[96][64];
    __shared__ float wv[33];
    int tile = blockIdx.x, h = blockIdx.y, b = blockIdx.z;
    int tid = threadIdx.x;
    if (tid < 33) wv[tid] = cw[h * 33 + tid];
    int i0 = tile * 64;
    for (int idx = tid; idx < 96 * 64; idx += 256) {
        int tt = idx >> 6, d = idx & 63;
        int tok = i0 - 16 + tt;
        float val = 0.f;
        if (tok >= 0 && tok < 4096)
            val = qkv[((long)(b * 4096 + tok)) * 1536 + 1024 + h * 64 + d];
        vs[tt][d] = val;
    }
    __syncthreads();
    int d = tid & 63, tr = tid >> 6;
    int z = b * 8 + h;
    for (int s = 0; s < 16; s++) {
        int tl = tr + s * 4;
        float acc = 0.f;
#pragma unroll
        for (int kk = 0; kk < 33; kk++) acc += wv[kk] * vs[tl + kk][d];
        int i = i0 + tl;
        float o = outh[((long)z * 4096 + i) * 64 + d] + acc;
        cat[((long)(b * 4096 + i)) * 512 + h * 64 + d] = o;
    }
}

// ---------------- launch ----------------
extern "C" void kernel_launch(void* const* d_in, const int* in_sizes, int n_in,
                              void* d_out, int out_size) {
    const float* x     = (const float*)d_in[0];
    const float* gamma = (const float*)d_in[1];
    const float* beta  = (const float*)d_in[2];
    const float* Wqkv  = (const float*)d_in[3];
    const float* Wout  = (const float*)d_in[4];
    const float* bout  = (const float*)d_in[5];
    const float* convw = (const float*)d_in[6];
    float* out = (float*)d_out;

    float *xn, *qkv, *ql, *kl, *s1, *s3, *a2, *z, *z2, *W, *U, *V2, *P2, *a3v, *tt, *oh, *cat, *red;
    float2 *rs1, *rs3;
    cudaGetSymbolAddress((void**)&xn,  g_xn);
    cudaGetSymbolAddress((void**)&qkv, g_qkv);
    cudaGetSymbolAddress((void**)&ql,  g_ql);
    cudaGetSymbolAddress((void**)&kl,  g_kl);
    cudaGetSymbolAddress((void**)&s1,  g_sim1);
    cudaGetSymbolAddress((void**)&s3,  g_sim3);
    cudaGetSymbolAddress((void**)&a2,  g_a2);
    cudaGetSymbolAddress((void**)&z,   g_z);
    cudaGetSymbolAddress((void**)&z2,  g_z2);
    cudaGetSymbolAddress((void**)&W,   g_W);
    cudaGetSymbolAddress((void**)&U,   g_U);
    cudaGetSymbolAddress((void**)&V2,  g_V2);
    cudaGetSymbolAddress((void**)&P2,  g_P2);
    cudaGetSymbolAddress((void**)&a3v, g_a3v);
    cudaGetSymbolAddress((void**)&tt,  g_t);
    cudaGetSymbolAddress((void**)&oh,  g_outh);
    cudaGetSymbolAddress((void**)&cat, g_cat);
    cudaGetSymbolAddress((void**)&red, g_red);
    cudaGetSymbolAddress((void**)&rs1, g_rs1);
    cudaGetSymbolAddress((void**)&rs3, g_rs3);

    // 1) LayerNorm
    ln_kernel<<<16384, 256>>>(x, gamma, beta, xn);

    // 2) QKV projection
    gemmT<128,128,2,4,false,1,false,false><<<dim3(12, 128, 1), 256>>>(
        xn, 512, 0, 0, Wqkv, 1536, 0, 0, qkv, 1536, 0, 0, 512, 0.f, 0.f,
        nullptr, nullptr, nullptr, nullptr, 0);

    // 3) landmarks
    landmark_kernel<<<dim3(256, 32), 64>>>(qkv, ql, kl);

    // 4) sim1 = q @ k_l^T  (raw)
    gemmT<128,128,2,4,true,0,false,false><<<dim3(2, 32, 32), 256>>>(
        qkv, 1536, 6291456, 64, kl, 64, 131072, 16384,
        s1, 256, 8388608, 1048576, 64, 0.f, 0.f, nullptr, nullptr, nullptr, nullptr, 0);
    // 5) sim2 = q_l @ k_l^T
    gemmT<128,128,2,4,true,0,false,false><<<dim3(2, 2, 32), 256>>>(
        ql, 64, 131072, 16384, kl, 64, 131072, 16384,
        a2, 256, 524288, 65536, 64, 0.f, 0.f, nullptr, nullptr, nullptr, nullptr, 0);
    // 6) sim3 = q_l @ k^T (raw)
    gemmT<128,128,2,4,true,0,false,false><<<dim3(32, 2, 32), 256>>>(
        ql, 64, 131072, 16384, qkv + 512, 1536, 6291456, 64,
        s3, 4096, 8388608, 1048576, 64, 0.f, 0.f, nullptr, nullptr, nullptr, nullptr, 0);

    // 7) a2 softmax (materialized; reused 7x by pinv) + row stats for s1, s3
    softmax_kernel<1><<<8192, 256>>>(a2);
    rowstat_kernel<1><<<131072, 256>>>(s1, rs1);
    rowstat_kernel<16><<<8192, 256>>>(s3, rs3);

    // 8) pinv init
    zero2<<<1, 1>>>(red);
    pinv_norms<<<32, 256>>>(a2, red);
    build_z0<<<8192, 256>>>(a2, z, red);

    // 9) 6 Newton-Schulz iterations (U = 7I - W fused into W-GEMM epilogue)
    float *zc = z, *zn = z2;
    for (int it = 0; it < 6; it++) {
        gemmT<128,128,2,4,false,4,false,false><<<dim3(2, 2, 32), 256>>>(   // W = a2@z, U = 7I-W
            a2, 256, 524288, 65536, zc, 256, 524288, 65536,
            W, 256, 524288, 65536, 256, 1.f, 7.f, nullptr, nullptr, U, nullptr, 0);
        gemmT<128,128,2,4,false,2,false,false><<<dim3(2, 2, 32), 256>>>(   // V2 = 15I - W@U
            W, 256, 524288, 65536, U, 256, 524288, 65536,
            V2, 256, 524288, 65536, 256, -1.f, 15.f, nullptr, nullptr, nullptr, nullptr, 0);
        gemmT<128,128,2,4,false,2,false,false><<<dim3(2, 2, 32), 256>>>(   // P2 = 13I - W@V2
            W, 256, 524288, 65536, V2, 256, 524288, 65536,
            P2, 256, 524288, 65536, 256, -1.f, 13.f, nullptr, nullptr, nullptr, nullptr, 0);
        gemmT<128,128,2,4,false,2,false,false><<<dim3(2, 2, 32), 256>>>(   // z' = 0.25 z@P2
            zc, 256, 524288, 65536, P2, 256, 524288, 65536,
            zn, 256, 524288, 65536, 256, 0.25f, 0.f, nullptr, nullptr, nullptr, nullptr, 0);
        float* tmp = zc; zc = zn; zn = tmp;
    }

    // 10) a3v = softmax(s3) @ v  — softmax fused on load, split-K=4 with atomics
    cudaMemsetAsync(a3v, 0, (size_t)32 * 256 * 64 * sizeof(float));
    gemmT<128,64,4,2,false,0,true,true><<<dim3(4, 2, 32), 256>>>(
        s3, 4096, 8388608, 1048576, qkv + 1024, 1536, 6291456, 64,
        a3v, 64, 131072, 16384, 1024, 0.f, 0.f, nullptr, nullptr, nullptr, rs3, 256);
    // 11) t = a2_inv @ a3v
    gemmT<128,64,4,2,false,0,false,false><<<dim3(1, 2, 32), 256>>>(
        zc, 256, 524288, 65536, a3v, 64, 131072, 16384,
        tt, 64, 131072, 16384, 256, 0.f, 0.f, nullptr, nullptr, nullptr, nullptr, 0);
    // 12) out_h = softmax(s1) @ t — softmax fused on load
    gemmT<128,64,4,2,false,0,true,false><<<dim3(1, 32, 32), 256>>>(
        s1, 256, 8388608, 1048576, tt, 64, 131072, 16384,
        oh, 64, 2097152, 262144, 256, 0.f, 0.f, nullptr, nullptr, nullptr, rs1, 4096);

    // 13) depthwise conv residual + head re-layout
    conv_add_cat<<<dim3(64, 8, 4), 256>>>(qkv, convw, oh, cat);

    // 14) out = x + cat @ W_out + b_out
    gemmT<128,128,2,4,false,3,false,false><<<dim3(4, 128, 1), 256>>>(
        cat, 512, 0, 0, Wout, 512, 0, 0, out, 512, 0, 0, 512, 0.f, 0.f,
        bout, x, nullptr, nullptr, 0);
}

// round 4
// speedup vs baseline: 2.9322x; 1.1582x over previous
#include <cuda_runtime.h>
#include <math.h>
#include <stdint.h>

// ---------------- static scratch (no allocations allowed) ----------------
__device__ float g_xn  [4*4096*512];
__device__ float g_qkv [4*4096*1536];
__device__ float g_ql  [32*256*64];
__device__ float g_kl  [32*256*64];
__device__ float g_a2  [32*256*256];
__device__ float g_z   [32*256*256];
__device__ float g_z2  [32*256*256];
__device__ float g_W   [32*256*256];
__device__ float g_U   [32*256*256];
__device__ float g_V2  [32*256*256];
__device__ float g_P2  [32*256*256];
__device__ float g_a3v [32*256*64];
__device__ float g_t   [32*256*64];
__device__ float g_outh[32*4096*64];
__device__ float g_cat [4*4096*512];
__device__ float g_red [2];
__device__ float g_part[32*8*256*64];   // flash3 split partials
__device__ float2 g_pst[32*8*256];      // flash3 split stats (m, l)

// ---------------- helpers ----------------
__device__ __forceinline__ float tf32r(float x) {
    uint32_t u;
    asm("cvt.rna.tf32.f32 %0, %1;" : "=r"(u) : "f"(x));
    return __uint_as_float(u);
}

__device__ __forceinline__ void mma8(float* c, const uint32_t* a, const uint32_t* b) {
    asm volatile(
        "mma.sync.aligned.m16n8k8.row.col.f32.tf32.tf32.f32 "
        "{%0,%1,%2,%3}, {%4,%5,%6,%7}, {%8,%9}, {%0,%1,%2,%3};\n"
        : "+f"(c[0]), "+f"(c[1]), "+f"(c[2]), "+f"(c[3])
        : "r"(a[0]), "r"(a[1]), "r"(a[2]), "r"(a[3]), "r"(b[0]), "r"(b[1]));
}

__device__ __forceinline__ void ldsm4(uint32_t* r, uint32_t addr) {
    asm volatile("ldmatrix.sync.aligned.m8n8.x4.shared.b16 {%0,%1,%2,%3}, [%4];\n"
        : "=r"(r[0]), "=r"(r[1]), "=r"(r[2]), "=r"(r[3]) : "r"(addr));
}

// ---------------- LayerNorm ----------------
__global__ void ln_kernel(const float* __restrict__ x, const float* __restrict__ gamma,
                          const float* __restrict__ beta, float* __restrict__ xn) {
    long row = blockIdx.x;
    const float* xr = x + row * 512;
    int t = threadIdx.x;
    float v0 = xr[t], v1 = xr[t + 256];
    __shared__ float red[256];
    red[t] = v0 + v1; __syncthreads();
    for (int s = 128; s; s >>= 1) { if (t < s) red[t] += red[t + s]; __syncthreads(); }
    float mu = red[0] * (1.f / 512.f); __syncthreads();
    float d0 = v0 - mu, d1 = v1 - mu;
    red[t] = d0 * d0 + d1 * d1; __syncthreads();
    for (int s = 128; s; s >>= 1) { if (t < s) red[t] += red[t + s]; __syncthreads(); }
    float rstd = rsqrtf(red[0] * (1.f / 512.f) + 1e-5f);
    float* o = xn + row * 512;
    o[t]       = d0 * rstd * gamma[t]       + beta[t];
    o[t + 256] = d1 * rstd * gamma[t + 256] + beta[t + 256];
}

// ---------------- TF32 tensor-core batched GEMM ----------------
// MODE 0: C=acc
// MODE 1: qkv epilogue (cols<512 scaled by 0.125)
// MODE 2: C = alpha*acc + dscale*I
// MODE 3: C = acc + bias[c] + resid[r*ldc+c]
// MODE 4: C = acc ; Caux = dscale*I - acc
template<int BM, int BN, int WR, int WC, bool BT, int MODE>
__global__ void __launch_bounds__(256)
gemmT(const float* __restrict__ A, int lda, long sAb, long sAh,
      const float* __restrict__ B, int ldb, long sBb, long sBh,
      float* __restrict__ C, int ldc, long sCb, long sCh,
      int K, float alpha, float dscale,
      const float* __restrict__ bias, const float* __restrict__ resid,
      float* __restrict__ Caux) {
    constexpr int WM = BM / WR, WN = BN / WC;
    constexpr int MT = WM / 16, NT = WN / 8;
    constexpr int AP = 20;        // A smem pitch: [BM][AP], k-inner
    constexpr int BP = BN + 8;    // B smem pitch: [16][BP], n-inner
    constexpr int AIT = BM * 16 / 1024;
    constexpr int BIT = BN * 16 / 1024;

    __shared__ __align__(16) float As[BM][AP];
    __shared__ __align__(16) float Bs[16][BP];

    int z = blockIdx.z;
    A += (long)(z >> 3) * sAb + (long)(z & 7) * sAh;
    B += (long)(z >> 3) * sBb + (long)(z & 7) * sBh;
    C += (long)(z >> 3) * sCb + (long)(z & 7) * sCh;
    if (MODE == 4) Caux += (long)(z >> 3) * sCb + (long)(z & 7) * sCh;

    const int col0 = blockIdx.x * BN;
    const int row0 = blockIdx.y * BM;
    const int tid = threadIdx.x, lane = tid & 31, wid = tid >> 5;
    const int wr = wid % WR, wc = wid / WR;
    const int g = lane >> 2, t4 = lane & 3;
    const int lrow = (lane & 7) + ((lane >> 3) & 1) * 8;
    const int lcol = ((lane >> 4) & 1) * 4;
    const uint32_t asBase = (uint32_t)__cvta_generic_to_shared(&As[0][0]);

    float acc[MT][NT][4];
#pragma unroll
    for (int i = 0; i < MT; i++)
#pragma unroll
        for (int j = 0; j < NT; j++)
#pragma unroll
            for (int e = 0; e < 4; e++) acc[i][j][e] = 0.f;

    float4 ra[AIT], rb[BIT];

    auto ldg = [&](int k0) {
#pragma unroll
        for (int i = 0; i < AIT; i++) {
            int idx = tid + i * 256;
            int r = idx >> 2, c4 = (idx & 3) << 2;
            ra[i] = *(const float4*)(A + (long)(row0 + r) * lda + k0 + c4);
        }
        if (BT) {
#pragma unroll
            for (int i = 0; i < BIT; i++) {
                int idx = tid + i * 256;
                int n = idx >> 2, c4 = (idx & 3) << 2;
                rb[i] = *(const float4*)(B + (long)(col0 + n) * ldb + k0 + c4);
            }
        } else {
#pragma unroll
            for (int i = 0; i < BIT; i++) {
                int idx = tid + i * 256;
                int r  = (BIT == 2) ? (idx >> 5) : (idx >> 4);
                int n4 = (BIT == 2) ? ((idx & 31) << 2) : ((idx & 15) << 2);
                rb[i] = *(const float4*)(B + (long)(k0 + r) * ldb + col0 + n4);
            }
        }
    };

    auto sts = [&]() {
#pragma unroll
        for (int i = 0; i < AIT; i++) {
            int idx = tid + i * 256;
            int r = idx >> 2, c4 = (idx & 3) << 2;
            float4 v = ra[i];
            v.x = tf32r(v.x); v.y = tf32r(v.y); v.z = tf32r(v.z); v.w = tf32r(v.w);
            *(float4*)&As[r][c4] = v;
        }
        if (BT) {
#pragma unroll
            for (int i = 0; i < BIT; i++) {
                int idx = tid + i * 256;
                int n = idx >> 2, c4 = (idx & 3) << 2;
                Bs[c4 + 0][n] = tf32r(rb[i].x);
                Bs[c4 + 1][n] = tf32r(rb[i].y);
                Bs[c4 + 2][n] = tf32r(rb[i].z);
                Bs[c4 + 3][n] = tf32r(rb[i].w);
            }
        } else {
#pragma unroll
            for (int i = 0; i < BIT; i++) {
                int idx = tid + i * 256;
                int r  = (BIT == 2) ? (idx >> 5) : (idx >> 4);
                int n4 = (BIT == 2) ? ((idx & 31) << 2) : ((idx & 15) << 2);
                float4 v = rb[i];
                v.x = tf32r(v.x); v.y = tf32r(v.y); v.z = tf32r(v.z); v.w = tf32r(v.w);
                *(float4*)&Bs[r][n4] = v;
            }
        }
    };

    ldg(0);
    for (int k0 = 0; k0 < K; k0 += 16) {
        sts();
        __syncthreads();
        if (k0 + 16 < K) ldg(k0 + 16);
#pragma unroll
        for (int k8 = 0; k8 < 16; k8 += 8) {
            uint32_t af[MT][4], bf[NT][2];
#pragma unroll
            for (int mt = 0; mt < MT; mt++) {
                int row = wr * WM + mt * 16 + lrow;
                ldsm4(af[mt], asBase + (uint32_t)((row * AP + lcol + k8) << 2));
            }
#pragma unroll
            for (int nt = 0; nt < NT; nt++) {
                int n0 = wc * WN + nt * 8 + g;
                bf[nt][0] = __float_as_uint(Bs[k8 + t4    ][n0]);
                bf[nt][1] = __float_as_uint(Bs[k8 + t4 + 4][n0]);
            }
#pragma unroll
            for (int mt = 0; mt < MT; mt++)
#pragma unroll
                for (int nt = 0; nt < NT; nt++)
                    mma8(acc[mt][nt], af[mt], bf[nt]);
        }
        __syncthreads();
    }

    // epilogue
#pragma unroll
    for (int mt = 0; mt < MT; mt++) {
#pragma unroll
        for (int nt = 0; nt < NT; nt++) {
            int r = row0 + wr * WM + mt * 16 + g;
            int c = col0 + wc * WN + nt * 8 + 2 * t4;
#pragma unroll
            for (int half = 0; half < 2; half++) {
                int rr = r + half * 8;
                float v0 = acc[mt][nt][half * 2];
                float v1 = acc[mt][nt][half * 2 + 1];
                if (MODE == 1) { if (c < 512) { v0 *= 0.125f; v1 *= 0.125f; } }
                if (MODE == 2) {
                    v0 = alpha * v0 + ((rr == c)     ? dscale : 0.f);
                    v1 = alpha * v1 + ((rr == c + 1) ? dscale : 0.f);
                }
                if (MODE == 3) {
                    const float2 rx = *(const float2*)(resid + (long)rr * ldc + c);
                    v0 = v0 + bias[c]     + rx.x;
                    v1 = v1 + bias[c + 1] + rx.y;
                }
                float2 o; o.x = v0; o.y = v1;
                *(float2*)(C + (long)rr * ldc + c) = o;
                if (MODE == 4) {
                    float2 u;
                    u.x = ((rr == c)     ? dscale : 0.f) - v0;
                    u.y = ((rr == c + 1) ? dscale : 0.f) - v1;
                    *(float2*)(Caux + (long)rr * ldc + c) = u;
                }
            }
        }
    }
}

// ---------------- fused flash attention (online softmax, TF32 MMA) ----------
// out[rows,64] = softmax_row( A[rows,64] @ B[tokens,64]^T ) @ V[tokens,64]
// 8 warps, each warp owns 16 rows (m16 x n64 score tiles, chunked 64 tokens).
// SPLIT: per-(z,seg) partials (unnormalized out + (m,l) stats) for later merge.
template<int NCHUNK, bool SPLIT>
__global__ void __launch_bounds__(256, 2)
flash_attn(const float* __restrict__ Ab, long sAb, long sAh, int lda,
           const float* __restrict__ Bb, long sBb, long sBh, int ldb,
           const float* __restrict__ Vb, long sVb, long sVh, int ldv,
           float* __restrict__ Out, float2* __restrict__ Pst) {
    extern __shared__ float sm[];
    float* As = sm;                  // [128][68]
    float* Ps = sm + 128 * 68;       // [128][68]
    float* Bs = sm + 2 * 128 * 68;   // [64][68]
    float* Vs = Bs + 64 * 68;        // [64][68]

    const int z = blockIdx.z, seg = blockIdx.x;
    const int row0 = blockIdx.y * 128;
    const int rowsZ = gridDim.y * 128;
    const float* A = Ab + (long)(z >> 3) * sAb + (long)(z & 7) * sAh;
    const float* B = Bb + (long)(z >> 3) * sBb + (long)(z & 7) * sBh;
    const float* V = Vb + (long)(z >> 3) * sVb + (long)(z & 7) * sVh;
    float* O = Out + (SPLIT ? (long)(z * gridDim.x + seg) * rowsZ * 64
                            : (long)z * rowsZ * 64);

    const int tid = threadIdx.x, lane = tid & 31, w = tid >> 5;
    const int g = lane >> 2, t4 = lane & 3;
    const int lrow = (lane & 7) + ((lane >> 3) & 1) * 8;
    const int lcol = ((lane >> 4) & 1) * 4;
    const uint32_t asB = (uint32_t)__cvta_generic_to_shared(As);
    const uint32_t psB = (uint32_t)__cvta_generic_to_shared(Ps);

    // load A tile (128 x 64) once
#pragma unroll
    for (int p = 0; p < 8; p++) {
        int idx = tid + p * 256;
        int r = idx >> 4, c4 = (idx & 15) << 2;
        float4 v = *(const float4*)(A + (long)(row0 + r) * lda + c4);
        v.x = tf32r(v.x); v.y = tf32r(v.y); v.z = tf32r(v.z); v.w = tf32r(v.w);
        *(float4*)&As[r * 68 + c4] = v;
    }

    float m0 = -INFINITY, m1 = -INFINITY, l0 = 0.f, l1 = 0.f;
    float ao[8][4] = {};
    const int tokBase = seg * NCHUNK * 64;
    const int rwa = w * 16 + g;   // warp-local row (g half)

    for (int c = 0; c < NCHUNK; c++) {
        int tok = tokBase + c * 64;
        __syncthreads();  // As ready (c==0) / prev chunk done with Bs,Vs
#pragma unroll
        for (int p = 0; p < 4; p++) {
            int idx = tid + p * 256;
            int n = idx >> 4, c4 = (idx & 15) << 2;
            float4 bv = *(const float4*)(B + (long)(tok + n) * ldb + c4);
            Bs[(c4 + 0) * 68 + n] = tf32r(bv.x);
            Bs[(c4 + 1) * 68 + n] = tf32r(bv.y);
            Bs[(c4 + 2) * 68 + n] = tf32r(bv.z);
            Bs[(c4 + 3) * 68 + n] = tf32r(bv.w);
        }
#pragma unroll
        for (int p = 0; p < 4; p++) {
            int idx = tid + p * 256;
            int k = idx >> 4, n4 = (idx & 15) << 2;
            float4 vv = *(const float4*)(V + (long)(tok + k) * ldv + n4);
            vv.x = tf32r(vv.x); vv.y = tf32r(vv.y); vv.z = tf32r(vv.z); vv.w = tf32r(vv.w);
            *(float4*)&Vs[k * 68 + n4] = vv;
        }
        __syncthreads();

        // scores: m16 x n64, K=64
        float sc[8][4] = {};
#pragma unroll
        for (int k8 = 0; k8 < 64; k8 += 8) {
            uint32_t af[4], bf[8][2];
            ldsm4(af, asB + (uint32_t)(((w * 16 + lrow) * 68 + k8 + lcol) << 2));
#pragma unroll
            for (int nt = 0; nt < 8; nt++) {
                bf[nt][0] = __float_as_uint(Bs[(k8 + t4) * 68 + nt * 8 + g]);
                bf[nt][1] = __float_as_uint(Bs[(k8 + t4 + 4) * 68 + nt * 8 + g]);
            }
#pragma unroll
            for (int nt = 0; nt < 8; nt++) mma8(sc[nt], af, bf[nt]);
        }

        // online softmax update (rows rwa and rwa+8; quad = lanes sharing g)
        float cm0 = -INFINITY, cm1 = -INFINITY;
#pragma unroll
        for (int nt = 0; nt < 8; nt++) {
            cm0 = fmaxf(cm0, fmaxf(sc[nt][0], sc[nt][1]));
            cm1 = fmaxf(cm1, fmaxf(sc[nt][2], sc[nt][3]));
        }
        cm0 = fmaxf(cm0, __shfl_xor_sync(0xffffffffu, cm0, 1));
        cm0 = fmaxf(cm0, __shfl_xor_sync(0xffffffffu, cm0, 2));
        cm1 = fmaxf(cm1, __shfl_xor_sync(0xffffffffu, cm1, 1));
        cm1 = fmaxf(cm1, __shfl_xor_sync(0xffffffffu, cm1, 2));
        float nm0 = fmaxf(m0, cm0), nm1 = fmaxf(m1, cm1);
        float f0 = __expf(m0 - nm0), f1 = __expf(m1 - nm1);
        l0 *= f0; l1 *= f1;
        float rs0 = 0.f, rs1 = 0.f;
#pragma unroll
        for (int nt = 0; nt < 8; nt++) {
            ao[nt][0] *= f0; ao[nt][1] *= f0; ao[nt][2] *= f1; ao[nt][3] *= f1;
            float p0 = __expf(sc[nt][0] - nm0), p1 = __expf(sc[nt][1] - nm0);
            float p2 = __expf(sc[nt][2] - nm1), p3 = __expf(sc[nt][3] - nm1);
            rs0 += p0 + p1; rs1 += p2 + p3;
            int col = nt * 8 + 2 * t4;
            float2 q0; q0.x = tf32r(p0); q0.y = tf32r(p1);
            float2 q1; q1.x = tf32r(p2); q1.y = tf32r(p3);
            *(float2*)&Ps[rwa * 68 + col] = q0;
            *(float2*)&Ps[(rwa + 8) * 68 + col] = q1;
        }
        rs0 += __shfl_xor_sync(0xffffffffu, rs0, 1);
        rs0 += __shfl_xor_sync(0xffffffffu, rs0, 2);
        rs1 += __shfl_xor_sync(0xffffffffu, rs1, 1);
        rs1 += __shfl_xor_sync(0xffffffffu, rs1, 2);
        l0 += rs0; l1 += rs1; m0 = nm0; m1 = nm1;
        __syncwarp();   // Ps rows are warp-private; make writes visible to ldmatrix

        // out += P @ V
#pragma unroll
        for (int k8 = 0; k8 < 64; k8 += 8) {
            uint32_t af[4], bf[8][2];
            ldsm4(af, psB + (uint32_t)(((w * 16 + lrow) * 68 + k8 + lcol) << 2));
#pragma unroll
            for (int nt = 0; nt < 8; nt++) {
                bf[nt][0] = __float_as_uint(Vs[(k8 + t4) * 68 + nt * 8 + g]);
                bf[nt][1] = __float_as_uint(Vs[(k8 + t4 + 4) * 68 + nt * 8 + g]);
            }
#pragma unroll
            for (int nt = 0; nt < 8; nt++) mma8(ao[nt], af, bf[nt]);
        }
    }

    // epilogue
    int ra = row0 + w * 16 + g;
    if (!SPLIT) {
        float i0 = 1.f / l0, i1 = 1.f / l1;
#pragma unroll
        for (int nt = 0; nt < 8; nt++) {
            int col = nt * 8 + 2 * t4;
            float2 o0; o0.x = ao[nt][0] * i0; o0.y = ao[nt][1] * i0;
            float2 o1; o1.x = ao[nt][2] * i1; o1.y = ao[nt][3] * i1;
            *(float2*)(O + (long)ra * 64 + col) = o0;
            *(float2*)(O + (long)(ra + 8) * 64 + col) = o1;
        }
    } else {
#pragma unroll
        for (int nt = 0; nt < 8; nt++) {
            int col = nt * 8 + 2 * t4;
            float2 o0; o0.x = ao[nt][0]; o0.y = ao[nt][1];
            float2 o1; o1.x = ao[nt][2]; o1.y = ao[nt][3];
            *(float2*)(O + (long)ra * 64 + col) = o0;
            *(float2*)(O + (long)(ra + 8) * 64 + col) = o1;
        }
        if (t4 == 0) {
            long sb = (long)(z * gridDim.x + seg) * rowsZ;
            float2 s0; s0.x = m0; s0.y = l0;
            float2 s1; s1.x = m1; s1.y = l1;
            Pst[sb + ra] = s0;
            Pst[sb + ra + 8] = s1;
        }
    }
}

// ---------------- merge flash3 split partials ----------------
__global__ void merge_split(const float* __restrict__ part, const float2* __restrict__ pst,
                            float* __restrict__ out) {
    long idx = (long)blockIdx.x * 256 + threadIdx.x;   // 32*256*64 elems
    int d = (int)(idx & 63);
    long zr = idx >> 6;                // z*256 + row
    int z = (int)(zr >> 8), row = (int)(zr & 255);
    float2 st[8];
    float M = -INFINITY;
#pragma unroll
    for (int s = 0; s < 8; s++) {
        st[s] = pst[((long)(z * 8 + s)) * 256 + row];
        M = fmaxf(M, st[s].x);
    }
    float L = 0.f, o = 0.f;
#pragma unroll
    for (int s = 0; s < 8; s++) {
        float e = __expf(st[s].x - M);
        L += st[s].y * e;
        o += part[(((long)(z * 8 + s)) * 256 + row) * 64 + d] * e;
    }
    out[zr * 64 + d] = o / L;
}

// ---------------- landmarks: mean over 16 contiguous tokens ----------------
__global__ void landmark_kernel(const float* __restrict__ qkv,
                                float* __restrict__ ql, float* __restrict__ kl) {
    int mi = blockIdx.x, z = blockIdx.y;
    int b = z >> 3, h = z & 7;
    int d = threadIdx.x;
    long base = ((long)(b * 4096 + mi * 16)) * 1536 + h * 64 + d;
    float sq = 0.f, sk = 0.f;
#pragma unroll
    for (int t = 0; t < 16; t++) {
        sq += qkv[base + (long)t * 1536];
        sk += qkv[base + (long)t * 1536 + 512];
    }
    long o = ((long)z * 256 + mi) * 64 + d;
    ql[o] = sq * 0.0625f;
    kl[o] = sk * 0.0625f;
}

// ---------------- row softmax for a2 (materialized; reused by pinv) --------
__global__ void softmax_kernel(float* __restrict__ p) {
    p += (long)blockIdx.x * 256;
    int t = threadIdx.x;
    float v = p[t];
    __shared__ float red[256];
    red[t] = v; __syncthreads();
    for (int s = 128; s; s >>= 1) { if (t < s) red[t] = fmaxf(red[t], red[t + s]); __syncthreads(); }
    float m = red[0]; __syncthreads();
    float e = expf(v - m);
    red[t] = e; __syncthreads();
    for (int s = 128; s; s >>= 1) { if (t < s) red[t] += red[t + s]; __syncthreads(); }
    p[t] = e / red[0];
}

// ---------------- pinv init ----------------
__global__ void zero2(float* r) { r[0] = 0.f; r[1] = 0.f; }

__global__ void pinv_norms(const float* __restrict__ a2, float* __restrict__ red) {
    int z = blockIdx.x, t = threadIdx.x;
    const float* a = a2 + (long)z * 65536;
    float cs = 0.f, rs = 0.f;
    for (int i = 0; i < 256; i++) cs += fabsf(a[i * 256 + t]);
    for (int j = 0; j < 256; j++) rs += fabsf(a[t * 256 + j]);
    __shared__ float s1[256], s2[256];
    s1[t] = cs; s2[t] = rs; __syncthreads();
    for (int s = 128; s; s >>= 1) {
        if (t < s) { s1[t] = fmaxf(s1[t], s1[t + s]); s2[t] = fmaxf(s2[t], s2[t + s]); }
        __syncthreads();
    }
    if (t == 0) {
        atomicMax((int*)&red[0], __float_as_int(s2[0]));   // col = sum(-1).max()
        atomicMax((int*)&red[1], __float_as_int(s1[0]));   // row = sum(-2).max()
    }
}

__global__ void build_z0(const float* __restrict__ a2, float* __restrict__ z0,
                         const float* __restrict__ red) {
    float inv = 1.f / (red[0] * red[1]);
    long idx = (long)blockIdx.x * 256 + threadIdx.x;
    long z = idx >> 16;
    int r = (int)(idx & 65535);
    int i = r >> 8, j = r & 255;
    z0[(z << 16) + ((long)j << 8) + i] = a2[idx] * inv;   // transpose
}

// ---------------- depthwise conv residual + head re-layout ----------------
__global__ void conv_add_cat(const float* __restrict__ qkv, const float* __restrict__ cw,
                             const float* __restrict__ outh, float* __restrict__ cat) {
    __shared__ float vs[96][64];
    __shared__ float wv[33];
    int tile = blockIdx.x, h = blockIdx.y, b = blockIdx.z;
    int tid = threadIdx.x;
    if (tid < 33) wv[tid] = cw[h * 33 + tid];
    int i0 = tile * 64;
    for (int idx = tid; idx < 96 * 64; idx += 256) {
        int tt = idx >> 6, d = idx & 63;
        int tok = i0 - 16 + tt;
        float val = 0.f;
        if (tok >= 0 && tok < 4096)
            val = qkv[((long)(b * 4096 + tok)) * 1536 + 1024 + h * 64 + d];
        vs[tt][d] = val;
    }
    __syncthreads();
    int d = tid & 63, tr = tid >> 6;
    int z = b * 8 + h;
    for (int s = 0; s < 16; s++) {
        int tl = tr + s * 4;
        float acc = 0.f;
#pragma unroll
        for (int kk = 0; kk < 33; kk++) acc += wv[kk] * vs[tl + kk][d];
        int i = i0 + tl;
        float o = outh[((long)z * 4096 + i) * 64 + d] + acc;
        cat[((long)(b * 4096 + i)) * 512 + h * 64 + d] = o;
    }
}

// ---------------- launch ----------------
extern "C" void kernel_launch(void* const* d_in, const int* in_sizes, int n_in,
                              void* d_out, int out_size) {
    const float* x     = (const float*)d_in[0];
    const float* gamma = (const float*)d_in[1];
    const float* beta  = (const float*)d_in[2];
    const float* Wqkv  = (const float*)d_in[3];
    const float* Wout  = (const float*)d_in[4];
    const float* bout  = (const float*)d_in[5];
    const float* convw = (const float*)d_in[6];
    float* out = (float*)d_out;

    float *xn, *qkv, *ql, *kl, *a2, *z, *z2, *W, *U, *V2, *P2, *a3v, *tt, *oh, *cat, *red, *part;
    float2 *pst;
    cudaGetSymbolAddress((void**)&xn,  g_xn);
    cudaGetSymbolAddress((void**)&qkv, g_qkv);
    cudaGetSymbolAddress((void**)&ql,  g_ql);
    cudaGetSymbolAddress((void**)&kl,  g_kl);
    cudaGetSymbolAddress((void**)&a2,  g_a2);
    cudaGetSymbolAddress((void**)&z,   g_z);
    cudaGetSymbolAddress((void**)&z2,  g_z2);
    cudaGetSymbolAddress((void**)&W,   g_W);
    cudaGetSymbolAddress((void**)&U,   g_U);
    cudaGetSymbolAddress((void**)&V2,  g_V2);
    cudaGetSymbolAddress((void**)&P2,  g_P2);
    cudaGetSymbolAddress((void**)&a3v, g_a3v);
    cudaGetSymbolAddress((void**)&tt,  g_t);
    cudaGetSymbolAddress((void**)&oh,  g_outh);
    cudaGetSymbolAddress((void**)&cat, g_cat);
    cudaGetSymbolAddress((void**)&red, g_red);
    cudaGetSymbolAddress((void**)&part, g_part);
    cudaGetSymbolAddress((void**)&pst, g_pst);

    const int FLASH_SMEM = (2 * 128 * 68 + 2 * 64 * 68) * 4;   // 104448 bytes
    cudaFuncSetAttribute(flash_attn<8, true>,
                         cudaFuncAttributeMaxDynamicSharedMemorySize, FLASH_SMEM);
    cudaFuncSetAttribute(flash_attn<4, false>,
                         cudaFuncAttributeMaxDynamicSharedMemorySize, FLASH_SMEM);

    // 1) LayerNorm
    ln_kernel<<<16384, 256>>>(x, gamma, beta, xn);

    // 2) QKV projection
    gemmT<128,128,2,4,false,1><<<dim3(12, 128, 1), 256>>>(
        xn, 512, 0, 0, Wqkv, 1536, 0, 0, qkv, 1536, 0, 0, 512, 0.f, 0.f,
        nullptr, nullptr, nullptr);

    // 3) landmarks
    landmark_kernel<<<dim3(256, 32), 64>>>(qkv, ql, kl);

    // 4) flash3: a3v partials = softmax(ql @ k^T) @ v, split over 8 token segments
    flash_attn<8, true><<<dim3(8, 2, 32), 256, FLASH_SMEM>>>(
        ql, 131072, 16384, 64,
        qkv + 512, 6291456, 64, 1536,
        qkv + 1024, 6291456, 64, 1536,
        part, pst);
    merge_split<<<2048, 256>>>(part, pst, a3v);

    // 5) sim2 = q_l @ k_l^T, softmax
    gemmT<128,128,2,4,true,0><<<dim3(2, 2, 32), 256>>>(
        ql, 64, 131072, 16384, kl, 64, 131072, 16384,
        a2, 256, 524288, 65536, 64, 0.f, 0.f, nullptr, nullptr, nullptr);
    softmax_kernel<<<8192, 256>>>(a2);

    // 6) pinv init
    zero2<<<1, 1>>>(red);
    pinv_norms<<<32, 256>>>(a2, red);
    build_z0<<<8192, 256>>>(a2, z, red);

    // 7) 6 Newton-Schulz iterations (128x64 tiles -> 256 blocks/step)
    float *zc = z, *zn = z2;
    for (int it = 0; it < 6; it++) {
        gemmT<128,64,4,2,false,4><<<dim3(4, 2, 32), 256>>>(   // W = a2@z, U = 7I-W
            a2, 256, 524288, 65536, zc, 256, 524288, 65536,
            W, 256, 524288, 65536, 256, 1.f, 7.f, nullptr, nullptr, U);
        gemmT<128,64,4,2,false,2><<<dim3(4, 2, 32), 256>>>(   // V2 = 15I - W@U
            W, 256, 524288, 65536, U, 256, 524288, 65536,
            V2, 256, 524288, 65536, 256, -1.f, 15.f, nullptr, nullptr, nullptr);
        gemmT<128,64,4,2,false,2><<<dim3(4, 2, 32), 256>>>(   // P2 = 13I - W@V2
            W, 256, 524288, 65536, V2, 256, 524288, 65536,
            P2, 256, 524288, 65536, 256, -1.f, 13.f, nullptr, nullptr, nullptr);
        gemmT<128,64,4,2,false,2><<<dim3(4, 2, 32), 256>>>(   // z' = 0.25 z@P2
            zc, 256, 524288, 65536, P2, 256, 524288, 65536,
            zn, 256, 524288, 65536, 256, 0.25f, 0.f, nullptr, nullptr, nullptr);
        float* tmp = zc; zc = zn; zn = tmp;
    }

    // 8) t = a2_inv @ a3v
    gemmT<128,64,4,2,false,0><<<dim3(1, 2, 32), 256>>>(
        zc, 256, 524288, 65536, a3v, 64, 131072, 16384,
        tt, 64, 131072, 16384, 256, 0.f, 0.f, nullptr, nullptr, nullptr);

    // 9) flash1: out_h = softmax(q @ kl^T) @ t
    flash_attn<4, false><<<dim3(1, 32, 32), 256, FLASH_SMEM>>>(
        qkv, 6291456, 64, 1536,
        kl, 131072, 16384, 64,
        tt, 131072, 16384, 64,
        oh, nullptr);

    // 10) depthwise conv residual + head re-layout
    conv_add_cat<<<dim3(64, 8, 4), 256>>>(qkv, convw, oh, cat);

    // 11) out = x + cat @ W_out + b_out
    gemmT<128,128,2,4,false,3><<<dim3(4, 128, 1), 256>>>(
        cat, 512, 0, 0, Wout, 512, 0, 0, out, 512, 0, 0, 512, 0.f, 0.f,
        bout, x, nullptr);
}